// round 2
// baseline (speedup 1.0000x reference)
#include <cuda_runtime.h>
#include <math.h>

// ---------------- problem constants ----------------
#define B_ 2
#define N_ 384
#define D_ 256
#define H_ 8
#define DH_ 32
#define PD_ 64
#define L_ 8
#define ROWS_ (B_*N_)      // 768
#define FF_ 1024
#define FEAT_ 320          // D + PD

// ---------------- scratch buffers (device globals; 16B-aligned for float4) ----------------
__device__ __align__(16) float g_x  [ROWS_*D_];
__device__ __align__(16) float g_tmp[ROWS_*D_];
__device__ __align__(16) float g_h  [ROWS_*D_];
__device__ __align__(16) float g_q  [ROWS_*D_];
__device__ __align__(16) float g_k  [ROWS_*D_];
__device__ __align__(16) float g_v  [ROWS_*D_];
__device__ __align__(16) float g_ao [ROWS_*D_];
__device__ __align__(16) float g_ffn[ROWS_*FF_];
__device__ __align__(16) float g_proj[ROWS_*PD_];
__device__ __align__(16) float g_pm  [ROWS_*PD_];
__device__ __align__(16) float g_feat[ROWS_*FEAT_];
__device__ __align__(16) float g_u   [ROWS_*128];
__device__ __align__(16) float g_t   [ROWS_*3];

// ---------------- reductions ----------------
__device__ __forceinline__ float2 block_sum2_256(float a, float b) {
    __shared__ float sa[8], sb[8];
    int lane = threadIdx.x & 31, wid = threadIdx.x >> 5;
#pragma unroll
    for (int o = 16; o > 0; o >>= 1) {
        a += __shfl_xor_sync(0xffffffffu, a, o);
        b += __shfl_xor_sync(0xffffffffu, b, o);
    }
    if (lane == 0) { sa[wid] = a; sb[wid] = b; }
    __syncthreads();
    if (threadIdx.x == 0) {
        float A = sa[0], Bv = sb[0];
        for (int w = 1; w < 8; w++) { A += sa[w]; Bv += sb[w]; }
        sa[0] = A; sb[0] = Bv;
    }
    __syncthreads();
    float2 r = make_float2(sa[0], sb[0]);
    __syncthreads();
    return r;
}

__device__ __forceinline__ float block_max_384(float v) {
    __shared__ float red[12];
    int lane = threadIdx.x & 31, wid = threadIdx.x >> 5;
#pragma unroll
    for (int o = 16; o > 0; o >>= 1) v = fmaxf(v, __shfl_xor_sync(0xffffffffu, v, o));
    if (lane == 0) red[wid] = v;
    __syncthreads();
    if (threadIdx.x == 0) {
        float m = red[0];
        for (int w = 1; w < 12; w++) m = fmaxf(m, red[w]);
        red[0] = m;
    }
    __syncthreads();
    float r = red[0];
    __syncthreads();
    return r;
}

__device__ __forceinline__ float block_sum_384(float v) {
    __shared__ float red[12];
    int lane = threadIdx.x & 31, wid = threadIdx.x >> 5;
#pragma unroll
    for (int o = 16; o > 0; o >>= 1) v += __shfl_xor_sync(0xffffffffu, v, o);
    if (lane == 0) red[wid] = v;
    __syncthreads();
    if (threadIdx.x == 0) {
        float s = red[0];
        for (int w = 1; w < 12; w++) s += red[w];
        red[0] = s;
    }
    __syncthreads();
    float r = red[0];
    __syncthreads();
    return r;
}

// ---------------- embedding + pos-enc + layernorm ----------------
__global__ void embed_kernel(const int* __restrict__ tokens,
                             const float* __restrict__ tok_emb,
                             const float* __restrict__ w,
                             const float* __restrict__ b,
                             float* __restrict__ out) {
    int row = blockIdx.x;
    int n = row % N_;
    int c = threadIdx.x;
    int tok = tokens[row];
    float val = tok_emb[tok * D_ + c];
    int half = c >> 1;
    float div = expf((float)(2 * half) * (-9.210340371976184f / (float)D_));
    float ang = (float)n * div;
    val += (c & 1) ? cosf(ang) : sinf(ang);
    float2 s = block_sum2_256(val, val * val);
    float m = s.x * (1.f / D_);
    float var = s.y * (1.f / D_) - m * m;
    out[row * D_ + c] = (val - m) * rsqrtf(var + 1e-5f) * w[c] + b[c];
}

// ---------------- layernorm over D=256 ----------------
__global__ void ln_kernel(const float* __restrict__ in,
                          const float* __restrict__ w,
                          const float* __restrict__ b,
                          float* __restrict__ out) {
    int row = blockIdx.x;
    int c = threadIdx.x;
    float v = in[row * D_ + c];
    float2 s = block_sum2_256(v, v * v);
    float m = s.x * (1.f / D_);
    float var = s.y * (1.f / D_) - m * m;
    out[row * D_ + c] = (v - m) * rsqrtf(var + 1e-5f) * w[c] + b[c];
}

// ---------------- generic tiled GEMM: C = act(A@B + bias (+ res)) ----------------
template <int ACT, bool RES>
__global__ void gemm_kernel(const float* __restrict__ A, const float* __restrict__ Bm,
                            const float* __restrict__ bias, const float* __restrict__ res,
                            float* __restrict__ C, int M, int N, int K) {
    __shared__ alignas(16) float As[16][64];
    __shared__ alignas(16) float Bs[16][64];
    int t = threadIdx.x;
    int tx = t & 15, ty = t >> 4;
    int m0 = blockIdx.y * 64, n0 = blockIdx.x * 64;
    int arow = t >> 2, ac4 = (t & 3) * 4;
    int brow = t >> 4, bc4 = (t & 15) * 4;
    float acc[4][4] = {};
    for (int k0 = 0; k0 < K; k0 += 16) {
        float4 av = *(const float4*)&A[(m0 + arow) * K + k0 + ac4];
        As[ac4 + 0][arow] = av.x; As[ac4 + 1][arow] = av.y;
        As[ac4 + 2][arow] = av.z; As[ac4 + 3][arow] = av.w;
        *(float4*)&Bs[brow][bc4] = *(const float4*)&Bm[(k0 + brow) * N + n0 + bc4];
        __syncthreads();
#pragma unroll
        for (int k = 0; k < 16; k++) {
            float4 ra = *(float4*)&As[k][ty * 4];
            float4 rb = *(float4*)&Bs[k][tx * 4];
            acc[0][0] += ra.x * rb.x; acc[0][1] += ra.x * rb.y; acc[0][2] += ra.x * rb.z; acc[0][3] += ra.x * rb.w;
            acc[1][0] += ra.y * rb.x; acc[1][1] += ra.y * rb.y; acc[1][2] += ra.y * rb.z; acc[1][3] += ra.y * rb.w;
            acc[2][0] += ra.z * rb.x; acc[2][1] += ra.z * rb.y; acc[2][2] += ra.z * rb.z; acc[2][3] += ra.z * rb.w;
            acc[3][0] += ra.w * rb.x; acc[3][1] += ra.w * rb.y; acc[3][2] += ra.w * rb.z; acc[3][3] += ra.w * rb.w;
        }
        __syncthreads();
    }
#pragma unroll
    for (int i = 0; i < 4; i++) {
        int m = m0 + ty * 4 + i;
#pragma unroll
        for (int j = 0; j < 4; j++) {
            int n = n0 + tx * 4 + j;
            float v = acc[i][j];
            if (bias) v += bias[n];
            if (RES) v += res[m * N + n];
            if (ACT == 1) v = fmaxf(v, 0.f);
            else if (ACT == 2) v = 0.5f * v * (1.f + erff(v * 0.7071067811865475f));
            else if (ACT == 3) v = v / (1.f + __expf(-v));
            C[m * N + n] = v;
        }
    }
}

// ---------------- fused SE3 attention: one block per (b,i), 384 threads ----------------
__global__ void attn_kernel(const float* __restrict__ Q, const float* __restrict__ K,
                            const float* __restrict__ V, const float* __restrict__ tb,
                            float* __restrict__ out) {
    int row = blockIdx.x;
    int b = row / N_;
    int t = threadIdx.x;
    __shared__ alignas(16) float qs[D_];
    __shared__ float sc[H_][N_];
    __shared__ float ti[3];
    __shared__ float inv_s[H_];
    __shared__ alignas(16) float avred[6][D_];

    if (t < D_) qs[t] = Q[row * D_ + t];
    if (t < 3) ti[t] = tb[row * 3 + t];
    __syncthreads();

    {
        int j = t;
        const float4* K4 = (const float4*)(K + (size_t)(b * N_ + j) * D_);
        float acc[H_];
#pragma unroll
        for (int h = 0; h < H_; h++) {
            float a = 0.f;
#pragma unroll
            for (int c4 = 0; c4 < 8; c4++) {
                float4 kv = K4[h * 8 + c4];
                float4 qv = *(const float4*)&qs[h * 32 + c4 * 4];
                a += kv.x * qv.x + kv.y * qv.y + kv.z * qv.z + kv.w * qv.w;
            }
            acc[h] = a;
        }
        float dx = tb[(b * N_ + j) * 3 + 0] - ti[0];
        float dy = tb[(b * N_ + j) * 3 + 1] - ti[1];
        float dz = tb[(b * N_ + j) * 3 + 2] - ti[2];
        float d2 = dx * dx + dy * dy + dz * dz;
        const float scale = 0.17677669529663687f;   // 1/sqrt(32)
#pragma unroll
        for (int h = 0; h < H_; h++) sc[h][j] = acc[h] * scale - d2;
    }
    __syncthreads();

#pragma unroll
    for (int h = 0; h < H_; h++) {
        float v = sc[h][t];
        float m = block_max_384(v);
        float e = __expf(v - m);
        sc[h][t] = e;
        float s = block_sum_384(e);
        if (t == 0) inv_s[h] = 1.f / s;
    }
    __syncthreads();

    {
        int g = t >> 6;
        int cg = t & 63;
        int h = cg >> 3;
        float4 o = make_float4(0.f, 0.f, 0.f, 0.f);
        for (int j = g; j < N_; j += 6) {
            float a = sc[h][j];
            float4 vv = *(const float4*)&V[(size_t)(b * N_ + j) * D_ + cg * 4];
            o.x += a * vv.x; o.y += a * vv.y; o.z += a * vv.z; o.w += a * vv.w;
        }
        *(float4*)&avred[g][cg * 4] = o;
    }
    __syncthreads();
    if (t < D_) {
        float s = 0.f;
#pragma unroll
        for (int g = 0; g < 6; g++) s += avred[g][t];
        out[row * D_ + t] = s * inv_s[t >> 5];
    }
}

// ---------------- fused pair LN + mean: one block per (b,i), 512 threads ----------------
__global__ void pair_kernel(const float* __restrict__ proj,
                            const float* __restrict__ relpos,
                            const float* __restrict__ pw,
                            const float* __restrict__ pb,
                            float* __restrict__ pm) {
    int row = blockIdx.x;
    int b = row / N_, i = row % N_;
    int t = threadIdx.x;
    int g = t >> 6;
    int c = t & 63;
    int lane = t & 31, wid = t >> 5;

    __shared__ float pi[PD_];
    __shared__ float red[16][2];
    __shared__ float accs[8][PD_];

    if (t < PD_) pi[t] = proj[row * PD_ + t];
    __syncthreads();

    float wc = pw[c], bc = pb[c];
    float picv = pi[c];
    float acc = 0.f;
    for (int j = g; j < N_; j += 8) {
        int rel = j - i;
        rel = min(64, max(-64, rel)) + 64;
        float v = picv + proj[(b * N_ + j) * PD_ + c] + relpos[rel * PD_ + c];
        float s = v, s2 = v * v;
#pragma unroll
        for (int o = 16; o > 0; o >>= 1) {
            s += __shfl_xor_sync(0xffffffffu, s, o);
            s2 += __shfl_xor_sync(0xffffffffu, s2, o);
        }
        if (lane == 0) { red[wid][0] = s; red[wid][1] = s2; }
        __syncthreads();
        int w0 = g * 2;
        float S = red[w0][0] + red[w0 + 1][0];
        float S2 = red[w0][1] + red[w0 + 1][1];
        float m = S * (1.f / PD_);
        float var = S2 * (1.f / PD_) - m * m;
        acc += (v - m) * rsqrtf(var + 1e-5f) * wc + bc;
        __syncthreads();
    }
    accs[g][c] = acc;
    __syncthreads();
    if (t < PD_) {
        float s = 0.f;
#pragma unroll
        for (int gg = 0; gg < 8; gg++) s += accs[gg][t];
        pm[row * PD_ + t] = s * (1.f / N_);
    }
}

// ---------------- concat [x, pm] -> feat ----------------
__global__ void concat_kernel(const float* __restrict__ x, const float* __restrict__ pm,
                              float* __restrict__ feat) {
    int row = blockIdx.x;
    int c = threadIdx.x;
    feat[row * FEAT_ + c] = (c < D_) ? x[row * D_ + c] : pm[row * PD_ + (c - D_)];
}

// ---------------- raw = u@Wf2 + bf2; rot6d; write frames + t ----------------
__global__ void frame_kernel(const float* __restrict__ u, const float* __restrict__ Wf2,
                             const float* __restrict__ bf2,
                             float* __restrict__ frames, float* __restrict__ tb) {
    int row = blockIdx.x;
    int t = threadIdx.x;
    __shared__ float us[128];
    __shared__ float raw[9];
    us[t] = u[row * 128 + t];
    __syncthreads();
    if (t < 9) {
        float s = bf2[t];
        for (int k = 0; k < 128; k++) s += us[k] * Wf2[k * 9 + t];
        raw[t] = s;
    }
    __syncthreads();
    if (t == 0) {
        float a1x = raw[0], a1y = raw[1], a1z = raw[2];
        float a2x = raw[3], a2y = raw[4], a2z = raw[5];
        float n1 = sqrtf(a1x * a1x + a1y * a1y + a1z * a1z + 1e-8f);
        float b1x = a1x / n1, b1y = a1y / n1, b1z = a1z / n1;
        float d = b1x * a2x + b1y * a2y + b1z * a2z;
        float px = a2x - d * b1x, py = a2y - d * b1y, pz = a2z - d * b1z;
        float n2 = sqrtf(px * px + py * py + pz * pz + 1e-8f);
        float b2x = px / n2, b2y = py / n2, b2z = pz / n2;
        float b3x = b1y * b2z - b1z * b2y;
        float b3y = b1z * b2x - b1x * b2z;
        float b3z = b1x * b2y - b1y * b2x;
        float tx = raw[6], ty = raw[7], tz = raw[8];
        float* F = frames + (size_t)row * 16;
        F[0] = b1x; F[1] = b1y; F[2] = b1z; F[3] = tx;
        F[4] = b2x; F[5] = b2y; F[6] = b2z; F[7] = ty;
        F[8] = b3x; F[9] = b3y; F[10] = b3z; F[11] = tz;
        F[12] = 0.f; F[13] = 0.f; F[14] = 0.f; F[15] = 1.f;
        tb[row * 3 + 0] = tx; tb[row * 3 + 1] = ty; tb[row * 3 + 2] = tz;
    }
}

// ---------------- utility ----------------
__global__ void zero_kernel(float* p, int n) {
    int i = blockIdx.x * blockDim.x + threadIdx.x;
    if (i < n) p[i] = 0.f;
}
__global__ void copy_kernel(const float* __restrict__ src, float* __restrict__ dst) {
    dst[blockIdx.x * blockDim.x + threadIdx.x] = src[blockIdx.x * blockDim.x + threadIdx.x];
}

// ---------------- host ----------------
extern "C" void kernel_launch(void* const* d_in, const int* in_sizes, int n_in,
                              void* d_out, int out_size) {
    (void)in_sizes; (void)n_in; (void)out_size;
    const int*   tokens     = (const int*)d_in[0];
    const float* tok_emb    = (const float*)d_in[1];
    const float* emb_ln_w   = (const float*)d_in[2];
    const float* emb_ln_b   = (const float*)d_in[3];
    const float* Wq         = (const float*)d_in[4];
    const float* Wk         = (const float*)d_in[5];
    const float* Wv         = (const float*)d_in[6];
    const float* Wo         = (const float*)d_in[7];
    const float* bo         = (const float*)d_in[8];
    const float* attn_ln_w  = (const float*)d_in[9];
    const float* attn_ln_b  = (const float*)d_in[10];
    const float* ff_ln_w    = (const float*)d_in[11];
    const float* ff_ln_b    = (const float*)d_in[12];
    const float* W1         = (const float*)d_in[13];
    const float* b1         = (const float*)d_in[14];
    const float* W2         = (const float*)d_in[15];
    const float* b2         = (const float*)d_in[16];
    const float* Wop        = (const float*)d_in[17];
    const float* bop        = (const float*)d_in[18];
    const float* relpos     = (const float*)d_in[19];
    const float* pair_ln_w  = (const float*)d_in[20];
    const float* pair_ln_b  = (const float*)d_in[21];
    const float* Wf1        = (const float*)d_in[22];
    const float* bf1        = (const float*)d_in[23];
    const float* Wf2        = (const float*)d_in[24];
    const float* bf2        = (const float*)d_in[25];

    float *x, *tmp, *h, *q, *k, *v, *ao, *ffn, *proj, *pm, *feat, *u, *tb;
    cudaGetSymbolAddress((void**)&x,   g_x);
    cudaGetSymbolAddress((void**)&tmp, g_tmp);
    cudaGetSymbolAddress((void**)&h,   g_h);
    cudaGetSymbolAddress((void**)&q,   g_q);
    cudaGetSymbolAddress((void**)&k,   g_k);
    cudaGetSymbolAddress((void**)&v,   g_v);
    cudaGetSymbolAddress((void**)&ao,  g_ao);
    cudaGetSymbolAddress((void**)&ffn, g_ffn);
    cudaGetSymbolAddress((void**)&proj,g_proj);
    cudaGetSymbolAddress((void**)&pm,  g_pm);
    cudaGetSymbolAddress((void**)&feat,g_feat);
    cudaGetSymbolAddress((void**)&u,   g_u);
    cudaGetSymbolAddress((void**)&tb,  g_t);

    float* fout = (float*)d_out;                 // frames: ROWS_*16
    float* xout = fout + ROWS_ * 16;             // x: ROWS_*D_

    zero_kernel<<<(ROWS_ * 3 + 255) / 256, 256>>>(tb, ROWS_ * 3);
    embed_kernel<<<ROWS_, 256>>>(tokens, tok_emb, emb_ln_w, emb_ln_b, x);

    for (int l = 0; l < L_; l++) {
        const float* Wql = Wq + (size_t)l * D_ * D_;
        const float* Wkl = Wk + (size_t)l * D_ * D_;
        const float* Wvl = Wv + (size_t)l * D_ * D_;
        const float* Wol = Wo + (size_t)l * D_ * D_;
        const float* bol = bo + (size_t)l * D_;
        const float* W1l = W1 + (size_t)l * D_ * FF_;
        const float* b1l = b1 + (size_t)l * FF_;
        const float* W2l = W2 + (size_t)l * FF_ * D_;
        const float* b2l = b2 + (size_t)l * D_;

        dim3 gD(D_ / 64, ROWS_ / 64);
        dim3 gFF(FF_ / 64, ROWS_ / 64);

        gemm_kernel<0, false><<<gD, 256>>>(x, Wql, nullptr, nullptr, q, ROWS_, D_, D_);
        gemm_kernel<0, false><<<gD, 256>>>(x, Wkl, nullptr, nullptr, k, ROWS_, D_, D_);
        gemm_kernel<0, false><<<gD, 256>>>(x, Wvl, nullptr, nullptr, v, ROWS_, D_, D_);

        attn_kernel<<<ROWS_, 384>>>(q, k, v, tb, ao);

        gemm_kernel<0, true><<<gD, 256>>>(ao, Wol, bol, x, tmp, ROWS_, D_, D_);
        ln_kernel<<<ROWS_, 256>>>(tmp, attn_ln_w + l * D_, attn_ln_b + l * D_, x);

        ln_kernel<<<ROWS_, 256>>>(x, ff_ln_w + l * D_, ff_ln_b + l * D_, h);
        gemm_kernel<2, false><<<gFF, 256>>>(h, W1l, b1l, nullptr, ffn, ROWS_, FF_, D_);
        gemm_kernel<0, true><<<gD, 256>>>(ffn, W2l, b2l, x, x, ROWS_, D_, FF_);

        gemm_kernel<1, false><<<dim3(1, ROWS_ / 64), 256>>>(x, Wop, bop, nullptr, proj, ROWS_, PD_, D_);

        pair_kernel<<<ROWS_, 512>>>(proj, relpos, pair_ln_w, pair_ln_b, pm);

        concat_kernel<<<ROWS_, FEAT_>>>(x, pm, feat);
        gemm_kernel<3, false><<<dim3(2, ROWS_ / 64), 256>>>(feat, Wf1, bf1, nullptr, u, ROWS_, 128, FEAT_);

        frame_kernel<<<ROWS_, 128>>>(u, Wf2, bf2, fout, tb);
    }

    copy_kernel<<<ROWS_, 256>>>(x, xout);
}

// round 3
// speedup vs baseline: 2.1382x; 2.1382x over previous
#include <cuda_runtime.h>
#include <math.h>

// ---------------- problem constants ----------------
#define B_ 2
#define N_ 384
#define D_ 256
#define H_ 8
#define DH_ 32
#define PD_ 64
#define L_ 8
#define ROWS_ (B_*N_)      // 768
#define FF_ 1024
#define FEAT_ 320          // D + PD

// ---------------- scratch buffers ----------------
__device__ __align__(16) float g_x   [ROWS_*D_];
__device__ __align__(16) float g_tmp [ROWS_*D_];
__device__ __align__(16) float g_h   [ROWS_*D_];
__device__ __align__(16) float g_qkv [3*ROWS_*D_];
__device__ __align__(16) float g_ao  [ROWS_*D_];
__device__ __align__(16) float g_ffn [ROWS_*FF_];
__device__ __align__(16) float g_s   [16*384*384];   // scores [b*8+h][i][j]
__device__ __align__(16) float g_proj[ROWS_*PD_];
__device__ __align__(16) float g_pm  [ROWS_*PD_];
__device__ __align__(16) float g_feat[ROWS_*FEAT_];
__device__ __align__(16) float g_u   [ROWS_*128];
__device__ __align__(16) float g_t   [ROWS_*3];

// ---------------- reductions ----------------
__device__ __forceinline__ float2 block_sum2_256(float a, float b) {
    __shared__ float sa[8], sb[8];
    int lane = threadIdx.x & 31, wid = threadIdx.x >> 5;
#pragma unroll
    for (int o = 16; o > 0; o >>= 1) {
        a += __shfl_xor_sync(0xffffffffu, a, o);
        b += __shfl_xor_sync(0xffffffffu, b, o);
    }
    if (lane == 0) { sa[wid] = a; sb[wid] = b; }
    __syncthreads();
    if (threadIdx.x == 0) {
        float A = sa[0], Bv = sb[0];
        for (int w = 1; w < 8; w++) { A += sa[w]; Bv += sb[w]; }
        sa[0] = A; sb[0] = Bv;
    }
    __syncthreads();
    float2 r = make_float2(sa[0], sb[0]);
    __syncthreads();
    return r;
}

// ---------------- embedding + pos-enc + layernorm ----------------
__global__ void embed_kernel(const int* __restrict__ tokens,
                             const float* __restrict__ tok_emb,
                             const float* __restrict__ w,
                             const float* __restrict__ b,
                             float* __restrict__ out) {
    int row = blockIdx.x;
    int n = row % N_;
    int c = threadIdx.x;
    int tok = tokens[row];
    float val = tok_emb[tok * D_ + c];
    int half = c >> 1;
    float div = expf((float)(2 * half) * (-9.210340371976184f / (float)D_));
    float ang = (float)n * div;
    val += (c & 1) ? cosf(ang) : sinf(ang);
    float2 s = block_sum2_256(val, val * val);
    float m = s.x * (1.f / D_);
    float var = s.y * (1.f / D_) - m * m;
    out[row * D_ + c] = (val - m) * rsqrtf(var + 1e-5f) * w[c] + b[c];
}

__global__ void ln_kernel(const float* __restrict__ in,
                          const float* __restrict__ w,
                          const float* __restrict__ b,
                          float* __restrict__ out) {
    int row = blockIdx.x;
    int c = threadIdx.x;
    float v = in[row * D_ + c];
    float2 s = block_sum2_256(v, v * v);
    float m = s.x * (1.f / D_);
    float var = s.y * (1.f / D_) - m * m;
    out[row * D_ + c] = (v - m) * rsqrtf(var + 1e-5f) * w[c] + b[c];
}

// ---------------- generic double-buffered GEMM ----------------
// MODE 0: plain C[M,N] = act(A[M,K] @ B[K,N] + bias (+res))
// MODE 1: QKV batched (z selects weight from {Bb0,Bb1,Bb2}, C += z*M*N)
// MODE 2: scores, batched over z=(b*8+h): A=Q(b,:,h), B=K(b,:,h) TRANSPOSED,
//         C[z] = (A@B^T)/sqrt(32) - d2(i,j)
// MODE 3: AV, batched: A=P[z], B=V(b,:,h), C=ao(b,:,h)
template<int M, int N, int K, int TM, int TN, int ACT, bool RES, int MODE>
__global__ __launch_bounds__(256) void gemm_k(
    const float* __restrict__ Abase, const float* __restrict__ Bb0,
    const float* __restrict__ Bb1,   const float* __restrict__ Bb2,
    const float* __restrict__ bias,  const float* __restrict__ res,
    float* __restrict__ Cbase,       const float* __restrict__ tb) {
    constexpr int TX = TN / 4;
    constexpr int TY = 256 / TX;
    constexpr int RM = TM / TY;
    constexpr int S  = K / 16;

    __shared__ alignas(16) float As[2][16][TM];
    __shared__ alignas(16) float Bs[2][16][TN];

    int t = threadIdx.x;
    int m0 = blockIdx.y * TM, n0 = blockIdx.x * TN;
    int z = blockIdx.z;

    const float* A; const float* Bp; float* C;
    int lda, ldb, ldc;
    int bidx = 0;
    if (MODE == 0) { A = Abase; Bp = Bb0; C = Cbase; lda = K; ldb = N; ldc = N; }
    else if (MODE == 1) {
        A = Abase; Bp = (z == 0) ? Bb0 : (z == 1) ? Bb1 : Bb2;
        C = Cbase + (size_t)z * M * N; lda = K; ldb = N; ldc = N;
    } else if (MODE == 2) {
        bidx = z >> 3; int h = z & 7;
        A  = Abase + (size_t)bidx * N_ * D_ + h * DH_;
        Bp = Bb0   + (size_t)bidx * N_ * D_ + h * DH_;
        C  = Cbase + (size_t)z * M * N;
        lda = D_; ldb = D_; ldc = N;
    } else {
        bidx = z >> 3; int h = z & 7;
        A  = Abase + (size_t)z * M * K;
        Bp = Bb0   + (size_t)bidx * N_ * D_ + h * DH_;
        C  = Cbase + (size_t)bidx * N_ * D_ + h * DH_;
        lda = K; ldb = D_; ldc = D_;
    }

    int tx = t % TX, ty = t / TX;

    float4 pa = make_float4(0.f,0.f,0.f,0.f), pb = pa;
    auto loadA = [&](int s, float4& r) {
        if (t < TM * 4) {
            int ar = t >> 2, ak = (t & 3) * 4;
            r = *(const float4*)&A[(size_t)(m0 + ar) * lda + s * 16 + ak];
        }
    };
    auto storeA = [&](int buf, const float4& r) {
        if (t < TM * 4) {
            int ar = t >> 2, ak = (t & 3) * 4;
            As[buf][ak + 0][ar] = r.x; As[buf][ak + 1][ar] = r.y;
            As[buf][ak + 2][ar] = r.z; As[buf][ak + 3][ar] = r.w;
        }
    };
    auto loadB = [&](int s, float4& r) {
        if (MODE == 2) {
            if (t < TN * 4) {
                int br = t >> 2, bk = (t & 3) * 4;
                r = *(const float4*)&Bp[(size_t)(n0 + br) * ldb + s * 16 + bk];
            }
        } else {
            if (t < TN * 4) {
                int br = t / TX, bc = (t % TX) * 4;
                r = *(const float4*)&Bp[(size_t)(s * 16 + br) * ldb + n0 + bc];
            }
        }
    };
    auto storeB = [&](int buf, const float4& r) {
        if (MODE == 2) {
            if (t < TN * 4) {
                int br = t >> 2, bk = (t & 3) * 4;
                Bs[buf][bk + 0][br] = r.x; Bs[buf][bk + 1][br] = r.y;
                Bs[buf][bk + 2][br] = r.z; Bs[buf][bk + 3][br] = r.w;
            }
        } else {
            if (t < TN * 4) {
                int br = t / TX, bc = (t % TX) * 4;
                *(float4*)&Bs[buf][br][bc] = r;
            }
        }
    };

    loadA(0, pa); loadB(0, pb);
    storeA(0, pa); storeB(0, pb);
    __syncthreads();

    float acc[RM][4];
#pragma unroll
    for (int i = 0; i < RM; i++)
#pragma unroll
        for (int j = 0; j < 4; j++) acc[i][j] = 0.f;

#pragma unroll 2
    for (int s = 0; s < S; s++) {
        int buf = s & 1;
        if (s + 1 < S) { loadA(s + 1, pa); loadB(s + 1, pb); }
#pragma unroll
        for (int k = 0; k < 16; k++) {
            float rb[4];
#pragma unroll
            for (int j = 0; j < 4; j++) rb[j] = Bs[buf][k][tx * 4 + j];
#pragma unroll
            for (int i = 0; i < RM; i++) {
                float ra = As[buf][k][ty * RM + i];
#pragma unroll
                for (int j = 0; j < 4; j++) acc[i][j] = fmaf(ra, rb[j], acc[i][j]);
            }
        }
        if (s + 1 < S) { storeA((s + 1) & 1, pa); storeB((s + 1) & 1, pb); }
        __syncthreads();
    }

    // epilogue
    float tix[RM], tiy[RM], tiz[RM], tjx[4], tjy[4], tjz[4];
    if (MODE == 2) {
        const float* tbb = tb + (size_t)bidx * N_ * 3;
#pragma unroll
        for (int i = 0; i < RM; i++) {
            int m = m0 + ty * RM + i;
            tix[i] = tbb[m * 3 + 0]; tiy[i] = tbb[m * 3 + 1]; tiz[i] = tbb[m * 3 + 2];
        }
#pragma unroll
        for (int j = 0; j < 4; j++) {
            int n = n0 + tx * 4 + j;
            tjx[j] = tbb[n * 3 + 0]; tjy[j] = tbb[n * 3 + 1]; tjz[j] = tbb[n * 3 + 2];
        }
    }
#pragma unroll
    for (int i = 0; i < RM; i++) {
        int m = m0 + ty * RM + i;
#pragma unroll
        for (int j = 0; j < 4; j++) {
            int n = n0 + tx * 4 + j;
            float v = acc[i][j];
            if (MODE == 2) {
                float dx = tix[i] - tjx[j], dy = tiy[i] - tjy[j], dz = tiz[i] - tjz[j];
                v = v * 0.17677669529663687f - (dx * dx + dy * dy + dz * dz);
            }
            if (bias) v += bias[n];
            if (RES) v += res[(size_t)m * ldc + n];
            if (ACT == 1) v = fmaxf(v, 0.f);
            else if (ACT == 2) v = 0.5f * v * (1.f + erff(v * 0.7071067811865475f));
            else if (ACT == 3) v = v / (1.f + __expf(-v));
            C[(size_t)m * ldc + n] = v;
        }
    }
}

// ---------------- warp-per-row softmax over S rows of length 384 ----------------
__global__ void softmax_kernel(float* __restrict__ S) {
    int r = blockIdx.x * 8 + (threadIdx.x >> 5);
    int l = threadIdx.x & 31;
    float* row = S + (size_t)r * 384;
    float v[12];
    float mx = -1e30f;
#pragma unroll
    for (int q = 0; q < 12; q++) { v[q] = row[l + q * 32]; mx = fmaxf(mx, v[q]); }
#pragma unroll
    for (int o = 16; o > 0; o >>= 1) mx = fmaxf(mx, __shfl_xor_sync(0xffffffffu, mx, o));
    float s = 0.f;
#pragma unroll
    for (int q = 0; q < 12; q++) { v[q] = __expf(v[q] - mx); s += v[q]; }
#pragma unroll
    for (int o = 16; o > 0; o >>= 1) s += __shfl_xor_sync(0xffffffffu, s, o);
    float inv = 1.f / s;
#pragma unroll
    for (int q = 0; q < 12; q++) row[l + q * 32] = v[q] * inv;
}

// ---------------- fused pair LN + mean: warp-per-j, 512 threads ----------------
__global__ __launch_bounds__(512) void pair_kernel(
        const float* __restrict__ proj, const float* __restrict__ relpos,
        const float* __restrict__ pw, const float* __restrict__ pb,
        float* __restrict__ pm) {
    int row = blockIdx.x;
    int b = row / N_, i = row % N_;
    int t = threadIdx.x;
    int w = t >> 5, l = t & 31;

    __shared__ float pi[PD_];
    __shared__ float accs[16][PD_];

    if (t < PD_) pi[t] = proj[row * PD_ + t];
    __syncthreads();

    float w0 = pw[l], w1 = pw[l + 32], bb0 = pb[l], bb1 = pb[l + 32];
    float p0 = pi[l], p1 = pi[l + 32];
    float a0 = 0.f, a1 = 0.f;
    for (int j = w; j < N_; j += 16) {
        int rel = min(64, max(-64, j - i)) + 64;
        const float* pj = proj + (size_t)(b * N_ + j) * PD_;
        const float* re = relpos + (size_t)rel * PD_;
        float v0 = p0 + pj[l] + re[l];
        float v1 = p1 + pj[l + 32] + re[l + 32];
        float s = v0 + v1, s2 = v0 * v0 + v1 * v1;
#pragma unroll
        for (int o = 16; o > 0; o >>= 1) {
            s  += __shfl_xor_sync(0xffffffffu, s, o);
            s2 += __shfl_xor_sync(0xffffffffu, s2, o);
        }
        float m = s * (1.f / PD_);
        float var = s2 * (1.f / PD_) - m * m;
        float rs = rsqrtf(var + 1e-5f);
        a0 += (v0 - m) * rs * w0 + bb0;
        a1 += (v1 - m) * rs * w1 + bb1;
    }
    accs[w][l] = a0; accs[w][l + 32] = a1;
    __syncthreads();
    if (t < PD_) {
        float s = 0.f;
#pragma unroll
        for (int ww = 0; ww < 16; ww++) s += accs[ww][t];
        pm[row * PD_ + t] = s * (1.f / N_);
    }
}

// ---------------- concat [x, pm] -> feat ----------------
__global__ void concat_kernel(const float* __restrict__ x, const float* __restrict__ pm,
                              float* __restrict__ feat) {
    int row = blockIdx.x;
    int c = threadIdx.x;
    feat[row * FEAT_ + c] = (c < D_) ? x[row * D_ + c] : pm[row * PD_ + (c - D_)];
}

// ---------------- raw = u@Wf2 + bf2; rot6d; frames + t ----------------
__global__ void frame_kernel(const float* __restrict__ u, const float* __restrict__ Wf2,
                             const float* __restrict__ bf2,
                             float* __restrict__ frames, float* __restrict__ tb) {
    int row = blockIdx.x;
    int t = threadIdx.x;
    __shared__ float us[128];
    __shared__ float raw[9];
    us[t] = u[row * 128 + t];
    __syncthreads();
    if (t < 9) {
        float s = bf2[t];
        for (int k = 0; k < 128; k++) s += us[k] * Wf2[k * 9 + t];
        raw[t] = s;
    }
    __syncthreads();
    if (t == 0) {
        float a1x = raw[0], a1y = raw[1], a1z = raw[2];
        float a2x = raw[3], a2y = raw[4], a2z = raw[5];
        float n1 = sqrtf(a1x * a1x + a1y * a1y + a1z * a1z + 1e-8f);
        float b1x = a1x / n1, b1y = a1y / n1, b1z = a1z / n1;
        float d = b1x * a2x + b1y * a2y + b1z * a2z;
        float px = a2x - d * b1x, py = a2y - d * b1y, pz = a2z - d * b1z;
        float n2 = sqrtf(px * px + py * py + pz * pz + 1e-8f);
        float b2x = px / n2, b2y = py / n2, b2z = pz / n2;
        float b3x = b1y * b2z - b1z * b2y;
        float b3y = b1z * b2x - b1x * b2z;
        float b3z = b1x * b2y - b1y * b2x;
        float tx = raw[6], ty = raw[7], tz = raw[8];
        float* F = frames + (size_t)row * 16;
        F[0] = b1x; F[1] = b1y; F[2]  = b1z; F[3]  = tx;
        F[4] = b2x; F[5] = b2y; F[6]  = b2z; F[7]  = ty;
        F[8] = b3x; F[9] = b3y; F[10] = b3z; F[11] = tz;
        F[12] = 0.f; F[13] = 0.f; F[14] = 0.f; F[15] = 1.f;
        tb[row * 3 + 0] = tx; tb[row * 3 + 1] = ty; tb[row * 3 + 2] = tz;
    }
}

// ---------------- utility ----------------
__global__ void zero_kernel(float* p, int n) {
    int i = blockIdx.x * blockDim.x + threadIdx.x;
    if (i < n) p[i] = 0.f;
}
__global__ void copy_kernel(const float* __restrict__ src, float* __restrict__ dst) {
    dst[blockIdx.x * blockDim.x + threadIdx.x] = src[blockIdx.x * blockDim.x + threadIdx.x];
}

// ---------------- host ----------------
extern "C" void kernel_launch(void* const* d_in, const int* in_sizes, int n_in,
                              void* d_out, int out_size) {
    (void)in_sizes; (void)n_in; (void)out_size;
    const int*   tokens     = (const int*)d_in[0];
    const float* tok_emb    = (const float*)d_in[1];
    const float* emb_ln_w   = (const float*)d_in[2];
    const float* emb_ln_b   = (const float*)d_in[3];
    const float* Wq         = (const float*)d_in[4];
    const float* Wk         = (const float*)d_in[5];
    const float* Wv         = (const float*)d_in[6];
    const float* Wo         = (const float*)d_in[7];
    const float* bo         = (const float*)d_in[8];
    const float* attn_ln_w  = (const float*)d_in[9];
    const float* attn_ln_b  = (const float*)d_in[10];
    const float* ff_ln_w    = (const float*)d_in[11];
    const float* ff_ln_b    = (const float*)d_in[12];
    const float* W1         = (const float*)d_in[13];
    const float* b1         = (const float*)d_in[14];
    const float* W2         = (const float*)d_in[15];
    const float* b2         = (const float*)d_in[16];
    const float* Wop        = (const float*)d_in[17];
    const float* bop        = (const float*)d_in[18];
    const float* relpos     = (const float*)d_in[19];
    const float* pair_ln_w  = (const float*)d_in[20];
    const float* pair_ln_b  = (const float*)d_in[21];
    const float* Wf1        = (const float*)d_in[22];
    const float* bf1        = (const float*)d_in[23];
    const float* Wf2        = (const float*)d_in[24];
    const float* bf2        = (const float*)d_in[25];

    float *x, *tmp, *h, *qkv, *ao, *ffn, *sbuf, *proj, *pm, *feat, *u, *tb;
    cudaGetSymbolAddress((void**)&x,   g_x);
    cudaGetSymbolAddress((void**)&tmp, g_tmp);
    cudaGetSymbolAddress((void**)&h,   g_h);
    cudaGetSymbolAddress((void**)&qkv, g_qkv);
    cudaGetSymbolAddress((void**)&ao,  g_ao);
    cudaGetSymbolAddress((void**)&ffn, g_ffn);
    cudaGetSymbolAddress((void**)&sbuf,g_s);
    cudaGetSymbolAddress((void**)&proj,g_proj);
    cudaGetSymbolAddress((void**)&pm,  g_pm);
    cudaGetSymbolAddress((void**)&feat,g_feat);
    cudaGetSymbolAddress((void**)&u,   g_u);
    cudaGetSymbolAddress((void**)&tb,  g_t);

    float* q = qkv;
    float* k = qkv + (size_t)ROWS_ * D_;
    float* v = qkv + (size_t)2 * ROWS_ * D_;

    float* fout = (float*)d_out;                 // frames: ROWS_*16
    float* xout = fout + ROWS_ * 16;             // x: ROWS_*D_

    zero_kernel<<<(ROWS_ * 3 + 255) / 256, 256>>>(tb, ROWS_ * 3);
    embed_kernel<<<ROWS_, 256>>>(tokens, tok_emb, emb_ln_w, emb_ln_b, x);

    for (int l = 0; l < L_; l++) {
        const float* Wql = Wq + (size_t)l * D_ * D_;
        const float* Wkl = Wk + (size_t)l * D_ * D_;
        const float* Wvl = Wv + (size_t)l * D_ * D_;
        const float* Wol = Wo + (size_t)l * D_ * D_;
        const float* bol = bo + (size_t)l * D_;
        const float* W1l = W1 + (size_t)l * D_ * FF_;
        const float* b1l = b1 + (size_t)l * FF_;
        const float* W2l = W2 + (size_t)l * FF_ * D_;
        const float* b2l = b2 + (size_t)l * D_;

        // fused QKV: grid (4,12,3) = 144 blocks
        gemm_k<ROWS_, D_, D_, 64, 64, 0, false, 1>
            <<<dim3(4, 12, 3), 256>>>(x, Wql, Wkl, Wvl, nullptr, nullptr, qkv, nullptr);

        // scores: S[z] = QK^T/sqrt(dh) - d2, grid (6,6,16) = 576 blocks
        gemm_k<384, 384, 32, 64, 64, 0, false, 2>
            <<<dim3(6, 6, 16), 256>>>(q, k, nullptr, nullptr, nullptr, nullptr, sbuf, tb);

        // softmax over j per (z,i) row
        softmax_kernel<<<768, 256>>>(sbuf);

        // AV: ao(b,:,h) = P[z] @ V(b,:,h), grid (1,6,16) = 96 blocks
        gemm_k<384, 32, 384, 64, 32, 0, false, 3>
            <<<dim3(1, 6, 16), 256>>>(sbuf, v, nullptr, nullptr, nullptr, nullptr, ao, nullptr);

        // tmp = x + ao@Wo + bo ; x = LN(tmp)
        gemm_k<ROWS_, D_, D_, 32, 64, 0, true, 0>
            <<<dim3(4, 24), 256>>>(ao, Wol, nullptr, nullptr, bol, x, tmp, nullptr);
        ln_kernel<<<ROWS_, 256>>>(tmp, attn_ln_w + l * D_, attn_ln_b + l * D_, x);

        // FFN
        ln_kernel<<<ROWS_, 256>>>(x, ff_ln_w + l * D_, ff_ln_b + l * D_, h);
        gemm_k<ROWS_, FF_, D_, 64, 64, 2, false, 0>
            <<<dim3(16, 12), 256>>>(h, W1l, nullptr, nullptr, b1l, nullptr, ffn, nullptr);
        gemm_k<ROWS_, D_, FF_, 32, 64, 0, true, 0>
            <<<dim3(4, 24), 256>>>(ffn, W2l, nullptr, nullptr, b2l, x, x, nullptr);

        // proj = relu(x@Wop + bop)
        gemm_k<ROWS_, PD_, D_, 32, 64, 1, false, 0>
            <<<dim3(1, 24), 256>>>(x, Wop, nullptr, nullptr, bop, nullptr, proj, nullptr);

        // pair LN + mean (fused)
        pair_kernel<<<ROWS_, 512>>>(proj, relpos, pair_ln_w, pair_ln_b, pm);

        // feat = [x, pm]; u = silu(feat@Wf1 + bf1)
        concat_kernel<<<ROWS_, FEAT_>>>(x, pm, feat);
        gemm_k<ROWS_, 128, FEAT_, 32, 64, 3, false, 0>
            <<<dim3(2, 24), 256>>>(feat, Wf1, nullptr, nullptr, bf1, nullptr, u, nullptr);

        // frames (into d_out) + t buffer
        frame_kernel<<<ROWS_, 128>>>(u, Wf2, bf2, fout, tb);
    }

    copy_kernel<<<ROWS_, 256>>>(x, xout);
}